// round 3
// baseline (speedup 1.0000x reference)
#include <cuda_runtime.h>
#include <cuda_bf16.h>
#include <cstdint>

// ---------------------------------------------------------------------------
// GAT layer:
//   h = x @ W.T                      [N,128] x [128,128]^T -> [N,128]
//   out = h; for each edge e: attn = leakyrelu(dot(h[src],a1)+dot(h[dst],a2))
//   out[dst] += 0.1 * attn * h[src]
//
// Kernel 1: tiled fp32 SGEMM writing h directly into d_out.
// Kernel 2: one block per edge; recompute h[src], h[dst] from x/W (never reads
//           the partially-updated output buffer), warp-per-head attention
//           reduction, atomicAdd into out[dst].
//
// NOTE: edge_index is int32 (jax x64 disabled downcasts jnp.int64 -> int32).
// ---------------------------------------------------------------------------

#define IN_F  128
#define OUT_F 128
#define HEADS 4
#define HDIM  32

// ---- GEMM: BM=64 rows, BN=128 cols (all), BK=16, 256 threads, TM=4 TN=8 ----
#define BM 64
#define BN 128
#define BK 16
#define TM 4
#define TN 8

__global__ __launch_bounds__(256) void gat_gemm_kernel(
    const float* __restrict__ X,   // [M,128]
    const float* __restrict__ W,   // [128,128]  (out = X * W^T)
    float* __restrict__ O,         // [M,128]
    int M)
{
    __shared__ float As[BK][BM];   // transposed X tile
    __shared__ float Bs[BK][BN];   // Bs[k][n] = W[n][k0+k]

    const int tid  = threadIdx.x;       // 0..255
    const int tcol = tid & 15;          // 0..15 -> N
    const int trow = tid >> 4;          // 0..15 -> M
    const int rowBase = blockIdx.x * BM;

    float acc[TM][TN];
    #pragma unroll
    for (int i = 0; i < TM; i++)
        #pragma unroll
        for (int j = 0; j < TN; j++) acc[i][j] = 0.0f;

    for (int k0 = 0; k0 < IN_F; k0 += BK) {
        // Load A tile: 64x16 = 1024 floats = 256 float4, 1 per thread.
        {
            int r  = tid >> 2;          // 0..63
            int c4 = tid & 3;           // 0..3
            int gr = rowBase + r;
            if (gr >= M) gr = M - 1;    // clamp (M divisible by 64 in practice)
            float4 v = *reinterpret_cast<const float4*>(
                X + (size_t)gr * IN_F + k0 + c4 * 4);
            As[c4 * 4 + 0][r] = v.x;
            As[c4 * 4 + 1][r] = v.y;
            As[c4 * 4 + 2][r] = v.z;
            As[c4 * 4 + 3][r] = v.w;
        }
        // Load B tile: 128x16 = 2048 floats = 512 float4, 2 per thread.
        #pragma unroll
        for (int i = 0; i < 2; i++) {
            int idx = tid + i * 256;    // 0..511
            int n   = idx >> 2;         // 0..127
            int c4  = idx & 3;          // 0..3
            float4 v = *reinterpret_cast<const float4*>(
                W + (size_t)n * IN_F + k0 + c4 * 4);
            Bs[c4 * 4 + 0][n] = v.x;
            Bs[c4 * 4 + 1][n] = v.y;
            Bs[c4 * 4 + 2][n] = v.z;
            Bs[c4 * 4 + 3][n] = v.w;
        }
        __syncthreads();

        #pragma unroll
        for (int k = 0; k < BK; k++) {
            float4 a4 = *reinterpret_cast<const float4*>(&As[k][trow * TM]);
            float ar[TM] = {a4.x, a4.y, a4.z, a4.w};
            float4 b0 = *reinterpret_cast<const float4*>(&Bs[k][tcol * TN]);
            float4 b1 = *reinterpret_cast<const float4*>(&Bs[k][tcol * TN + 4]);
            float br[TN] = {b0.x, b0.y, b0.z, b0.w, b1.x, b1.y, b1.z, b1.w};
            #pragma unroll
            for (int i = 0; i < TM; i++)
                #pragma unroll
                for (int j = 0; j < TN; j++)
                    acc[i][j] += ar[i] * br[j];
        }
        __syncthreads();
    }

    // Write out
    #pragma unroll
    for (int i = 0; i < TM; i++) {
        int gr = rowBase + trow * TM + i;
        if (gr < M) {
            float* op = O + (size_t)gr * OUT_F + tcol * TN;
            *reinterpret_cast<float4*>(op) =
                make_float4(acc[i][0], acc[i][1], acc[i][2], acc[i][3]);
            *reinterpret_cast<float4*>(op + 4) =
                make_float4(acc[i][4], acc[i][5], acc[i][6], acc[i][7]);
        }
    }
}

// ---- Edge kernel: one block (128 threads) per edge --------------------------
__global__ __launch_bounds__(128) void gat_edge_kernel(
    const float* __restrict__ X,
    const int* __restrict__ EI,        // [2,E] int32: row0 = src, row1 = dst
    const float* __restrict__ W,
    const float* __restrict__ A,       // [HEADS, 2*HDIM]
    float* __restrict__ O,
    int E)
{
    const int e = blockIdx.x;
    if (e >= E) return;
    const int tid = threadIdx.x;       // 0..127 == output feature index
    const int src = EI[e];
    const int dst = EI[E + e];

    __shared__ float xs[IN_F];
    __shared__ float xd[IN_F];
    xs[tid] = X[(size_t)src * IN_F + tid];
    xd[tid] = X[(size_t)dst * IN_F + tid];
    __syncthreads();

    // h_src[tid], h_dst[tid] = dot(x[*], W[tid])
    const float* wrow = W + (size_t)tid * IN_F;
    float hs = 0.0f, hd = 0.0f;
    #pragma unroll 8
    for (int k = 0; k < IN_F; k++) {
        float w = wrow[k];
        hs = fmaf(xs[k], w, hs);
        hd = fmaf(xd[k], w, hd);
    }

    // attention: warp per head (tid/32 == head, tid%32 == dim within head)
    const int h = tid >> 5;
    const int d = tid & 31;
    float ev = hs * A[h * (2 * HDIM) + d] + hd * A[h * (2 * HDIM) + HDIM + d];
    #pragma unroll
    for (int off = 16; off > 0; off >>= 1)
        ev += __shfl_xor_sync(0xffffffffu, ev, off);
    float attn = ev > 0.0f ? ev : 0.2f * ev;

    atomicAdd(&O[(size_t)dst * OUT_F + tid], 0.1f * attn * hs);
}

extern "C" void kernel_launch(void* const* d_in, const int* in_sizes, int n_in,
                              void* d_out, int out_size)
{
    const float* x  = (const float*)d_in[0];
    const int*   ei = (const int*)d_in[1];
    const float* W  = (const float*)d_in[2];
    const float* a  = (const float*)d_in[3];
    float* out = (float*)d_out;

    const int M = in_sizes[0] / IN_F;   // 200000
    const int E = in_sizes[1] / 2;      // 500

    const int grid = (M + BM - 1) / BM; // 3125
    gat_gemm_kernel<<<grid, 256>>>(x, W, out, M);
    gat_edge_kernel<<<E, 128>>>(x, ei, W, a, out, E);
}

// round 4
// speedup vs baseline: 3.4783x; 3.4783x over previous
#include <cuda_runtime.h>
#include <cuda_bf16.h>
#include <cstdint>

// ---------------------------------------------------------------------------
// GAT layer, tf32 tensor-core version.
//   K1: h = x @ W.T via mma.sync m16n8k8 tf32 -> writes d_out (=h).
//   K2: per edge, read h[src], h[dst] from d_out (pre-scatter), compute
//       leakyrelu attention, stage contribution 0.1*attn*h_src in scratch.
//   K3: atomicAdd staged contributions into d_out[dst].
// The K2/K3 split removes the read-after-scatter hazard on d_out.
// edge_index is int32 (jax x64 disabled).
// ---------------------------------------------------------------------------

#define IN_F  128
#define OUT_F 128
#define HEADS 4
#define HDIM  32

#define BM 64
#define LDSTR 132           // smem row stride in floats: 528B, 16B-aligned, conflict-free

#define MAX_E 2048
__device__ float g_contrib[MAX_E * OUT_F];

__device__ __forceinline__ uint32_t f2tf32(float f) {
    uint32_t u;
    asm("cvt.rna.tf32.f32 %0, %1;" : "=r"(u) : "f"(f));
    return u;
}

__device__ __forceinline__ void mma_tf32(float* c, const uint32_t* a, const uint32_t* b) {
    asm volatile(
        "mma.sync.aligned.m16n8k8.row.col.f32.tf32.tf32.f32 "
        "{%0,%1,%2,%3}, {%4,%5,%6,%7}, {%8,%9}, {%0,%1,%2,%3};"
        : "+f"(c[0]), "+f"(c[1]), "+f"(c[2]), "+f"(c[3])
        : "r"(a[0]), "r"(a[1]), "r"(a[2]), "r"(a[3]), "r"(b[0]), "r"(b[1]));
}

// ---- K1: tf32 GEMM. grid = M/64 blocks, 128 threads (4 warps). -------------
// Warp w computes rows [0,64) x cols [32w, 32w+32). Full K=128 staged once.
__global__ __launch_bounds__(128) void gat_gemm_tf32(
    const float* __restrict__ X,   // [M,128]
    const float* __restrict__ W,   // [128,128] row-major (out = X * W^T)
    float* __restrict__ O,         // [M,128]
    int M)
{
    extern __shared__ uint32_t smem[];
    uint32_t* As = smem;                    // [64][LDSTR]  (tf32 bits of X tile)
    uint32_t* Ws = smem + BM * LDSTR;       // [128][LDSTR] (tf32 bits of W)

    const int tid = threadIdx.x;
    const int rowBase = blockIdx.x * BM;

    // Stage X tile: 64x128 floats = 2048 float4, 16 per thread.
    #pragma unroll
    for (int i = 0; i < 16; i++) {
        int fid = tid + i * 128;
        int m = fid >> 5, c4 = fid & 31;
        int gr = rowBase + m; if (gr >= M) gr = M - 1;
        float4 v = *reinterpret_cast<const float4*>(X + (size_t)gr * IN_F + c4 * 4);
        uint4 t = make_uint4(f2tf32(v.x), f2tf32(v.y), f2tf32(v.z), f2tf32(v.w));
        *reinterpret_cast<uint4*>(As + m * LDSTR + c4 * 4) = t;
    }
    // Stage full W: 128x128 floats = 4096 float4, 32 per thread.
    #pragma unroll
    for (int i = 0; i < 32; i++) {
        int fid = tid + i * 128;
        int n = fid >> 5, c4 = fid & 31;
        float4 v = *reinterpret_cast<const float4*>(W + (size_t)n * IN_F + c4 * 4);
        uint4 t = make_uint4(f2tf32(v.x), f2tf32(v.y), f2tf32(v.z), f2tf32(v.w));
        *reinterpret_cast<uint4*>(Ws + n * LDSTR + c4 * 4) = t;
    }
    __syncthreads();

    const int warp = tid >> 5, lane = tid & 31;
    const int g = lane >> 2, tig = lane & 3;    // group row / thread-in-group
    const int nBase = warp * 32;

    float acc[4][4][4];
    #pragma unroll
    for (int mt = 0; mt < 4; mt++)
        #pragma unroll
        for (int nt = 0; nt < 4; nt++)
            #pragma unroll
            for (int r = 0; r < 4; r++) acc[mt][nt][r] = 0.0f;

    #pragma unroll
    for (int ks = 0; ks < 16; ks++) {
        const int k0 = ks * 8;
        uint32_t a[4][4];
        #pragma unroll
        for (int mt = 0; mt < 4; mt++) {
            int m0 = mt * 16 + g;
            a[mt][0] = As[m0 * LDSTR + k0 + tig];
            a[mt][1] = As[(m0 + 8) * LDSTR + k0 + tig];
            a[mt][2] = As[m0 * LDSTR + k0 + tig + 4];
            a[mt][3] = As[(m0 + 8) * LDSTR + k0 + tig + 4];
        }
        uint32_t b[4][2];
        #pragma unroll
        for (int nt = 0; nt < 4; nt++) {
            int n0 = nBase + nt * 8 + g;
            b[nt][0] = Ws[n0 * LDSTR + k0 + tig];
            b[nt][1] = Ws[n0 * LDSTR + k0 + tig + 4];
        }
        #pragma unroll
        for (int mt = 0; mt < 4; mt++)
            #pragma unroll
            for (int nt = 0; nt < 4; nt++)
                mma_tf32(acc[mt][nt], a[mt], b[nt]);
    }

    // Write: c0/c1 -> (row g, cols 2*tig, 2*tig+1); c2/c3 -> row g+8.
    #pragma unroll
    for (int mt = 0; mt < 4; mt++) {
        int r0 = rowBase + mt * 16 + g;
        int r1 = r0 + 8;
        #pragma unroll
        for (int nt = 0; nt < 4; nt++) {
            int c = nBase + nt * 8 + tig * 2;
            if (r0 < M)
                *reinterpret_cast<float2*>(O + (size_t)r0 * OUT_F + c) =
                    make_float2(acc[mt][nt][0], acc[mt][nt][1]);
            if (r1 < M)
                *reinterpret_cast<float2*>(O + (size_t)r1 * OUT_F + c) =
                    make_float2(acc[mt][nt][2], acc[mt][nt][3]);
        }
    }
}

// ---- K2: gather h from O, compute attn, stage contribution -----------------
__global__ __launch_bounds__(128) void gat_edge_gather(
    const float* __restrict__ O,
    const int* __restrict__ EI,        // [2,E]: row0 src, row1 dst
    const float* __restrict__ A,       // [HEADS, 2*HDIM]
    int E)
{
    const int e = blockIdx.x;
    const int tid = threadIdx.x;
    const int src = EI[e];
    const int dst = EI[E + e];

    float hs = O[(size_t)src * OUT_F + tid];
    float hd = O[(size_t)dst * OUT_F + tid];

    const int h = tid >> 5;
    const int d = tid & 31;
    float ev = hs * A[h * (2 * HDIM) + d] + hd * A[h * (2 * HDIM) + HDIM + d];
    #pragma unroll
    for (int off = 16; off > 0; off >>= 1)
        ev += __shfl_xor_sync(0xffffffffu, ev, off);
    float attn = ev > 0.0f ? ev : 0.2f * ev;

    g_contrib[e * OUT_F + tid] = 0.1f * attn * hs;
}

// ---- K3: scatter staged contributions --------------------------------------
__global__ __launch_bounds__(128) void gat_edge_scatter(
    float* __restrict__ O,
    const int* __restrict__ EI,
    int E)
{
    const int e = blockIdx.x;
    const int tid = threadIdx.x;
    const int dst = EI[E + e];
    atomicAdd(&O[(size_t)dst * OUT_F + tid], g_contrib[e * OUT_F + tid]);
}

extern "C" void kernel_launch(void* const* d_in, const int* in_sizes, int n_in,
                              void* d_out, int out_size)
{
    const float* x  = (const float*)d_in[0];
    const int*   ei = (const int*)d_in[1];
    const float* W  = (const float*)d_in[2];
    const float* a  = (const float*)d_in[3];
    float* out = (float*)d_out;

    const int M = in_sizes[0] / IN_F;   // 200000
    int E = in_sizes[1] / 2;            // 500
    if (E > MAX_E) E = MAX_E;

    const int smemBytes = (BM + IN_F) * LDSTR * sizeof(uint32_t);  // ~99KB
    cudaFuncSetAttribute(gat_gemm_tf32,
                         cudaFuncAttributeMaxDynamicSharedMemorySize, smemBytes);

    const int grid = (M + BM - 1) / BM;
    gat_gemm_tf32<<<grid, 128, smemBytes>>>(x, W, out, M);
    gat_edge_gather<<<E, 128>>>(out, ei, a, E);
    gat_edge_scatter<<<E, 128>>>(out, ei, E);
}

// round 5
// speedup vs baseline: 3.8649x; 1.1112x over previous
#include <cuda_runtime.h>
#include <cuda_bf16.h>
#include <cstdint>

// ---------------------------------------------------------------------------
// GAT layer, tf32 tensor-core version, ldmatrix fragment loads.
//   K1: h = x @ W.T via mma.sync m16n8k8 tf32 -> writes d_out (=h).
//   K2: per edge, read h[src], h[dst] from d_out (pre-scatter), attention,
//       stage 0.1*attn*h_src into scratch.
//   K3: atomicAdd staged contributions into d_out[dst].
// edge_index is int32 (jax x64 disabled).
// ---------------------------------------------------------------------------

#define IN_F  128
#define OUT_F 128
#define HEADS 4
#define HDIM  32

#define BM 64
#define LDSTR 132           // smem row stride (floats): 528B; LDSM rows hit
                            // 16r mod 128 -> 8 distinct 16B banks, conflict-free

#define MAX_E 2048
__device__ float g_contrib[MAX_E * OUT_F];

__device__ __forceinline__ uint32_t f2tf32(float f) {
    uint32_t u;
    asm("cvt.rna.tf32.f32 %0, %1;" : "=r"(u) : "f"(f));
    return u;
}

__device__ __forceinline__ uint32_t smem_u32(const void* p) {
    uint32_t a;
    asm("{ .reg .u64 t; cvta.to.shared.u64 t, %1; cvt.u32.u64 %0, t; }"
        : "=r"(a) : "l"(p));
    return a;
}

__device__ __forceinline__ void ldsm_x4(uint32_t& r0, uint32_t& r1,
                                        uint32_t& r2, uint32_t& r3,
                                        uint32_t addr) {
    asm volatile("ldmatrix.sync.aligned.m8n8.x4.shared.b16 {%0,%1,%2,%3}, [%4];"
                 : "=r"(r0), "=r"(r1), "=r"(r2), "=r"(r3) : "r"(addr));
}

__device__ __forceinline__ void mma_tf32(float* c, const uint32_t* a, const uint32_t* b) {
    asm volatile(
        "mma.sync.aligned.m16n8k8.row.col.f32.tf32.tf32.f32 "
        "{%0,%1,%2,%3}, {%4,%5,%6,%7}, {%8,%9}, {%0,%1,%2,%3};"
        : "+f"(c[0]), "+f"(c[1]), "+f"(c[2]), "+f"(c[3])
        : "r"(a[0]), "r"(a[1]), "r"(a[2]), "r"(a[3]), "r"(b[0]), "r"(b[1]));
}

// ---- K1: tf32 GEMM. grid = M/64, 128 threads (4 warps). --------------------
// Warp w: rows [0,64) x cols [32w, 32w+32). Full K=128 staged once.
__global__ __launch_bounds__(128, 2) void gat_gemm_tf32(
    const float* __restrict__ X,   // [M,128]
    const float* __restrict__ W,   // [128,128] row-major (out = X * W^T)
    float* __restrict__ O,         // [M,128]
    int M)
{
    extern __shared__ uint32_t smem[];
    uint32_t* As = smem;                    // [64][LDSTR]
    uint32_t* Ws = smem + BM * LDSTR;       // [128][LDSTR]

    const int tid = threadIdx.x;
    const int rowBase = blockIdx.x * BM;

    // Stage X tile: 64x128 = 2048 float4, 16 per thread.
    #pragma unroll
    for (int i = 0; i < 16; i++) {
        int fid = tid + i * 128;
        int m = fid >> 5, c4 = fid & 31;
        int gr = rowBase + m; if (gr >= M) gr = M - 1;
        float4 v = *reinterpret_cast<const float4*>(X + (size_t)gr * IN_F + c4 * 4);
        uint4 t = make_uint4(f2tf32(v.x), f2tf32(v.y), f2tf32(v.z), f2tf32(v.w));
        *reinterpret_cast<uint4*>(As + m * LDSTR + c4 * 4) = t;
    }
    // Stage full W: 128x128 = 4096 float4, 32 per thread.
    #pragma unroll
    for (int i = 0; i < 32; i++) {
        int fid = tid + i * 128;
        int n = fid >> 5, c4 = fid & 31;
        float4 v = *reinterpret_cast<const float4*>(W + (size_t)n * IN_F + c4 * 4);
        uint4 t = make_uint4(f2tf32(v.x), f2tf32(v.y), f2tf32(v.z), f2tf32(v.w));
        *reinterpret_cast<uint4*>(Ws + n * LDSTR + c4 * 4) = t;
    }
    __syncthreads();

    const int warp = tid >> 5, lane = tid & 31;
    const int g = lane >> 2, tig = lane & 3;
    const int nBase = warp * 32;

    // LDSM lane address bases (byte offsets advance by 32 per K-step).
    // A tile mt: row = mt*16 + (lane&7) + ((lane>>3)&1)*8, col = ((lane>>4)&1)*4
    //   -> blocks: a0(rows 0-7,k0..k0+3), a1(rows 8-15), a2(rows 0-7,k0+4..), a3.
    const int aRow = (lane & 7) + ((lane >> 3) & 1) * 8;
    const int aCol = ((lane >> 4) & 1) * 4;
    uint32_t aAddr[4];
    #pragma unroll
    for (int mt = 0; mt < 4; mt++)
        aAddr[mt] = smem_u32(As + (mt * 16 + aRow) * LDSTR + aCol);

    // B tile-pair j (n-tiles 2j,2j+1): row = n0 + (lane&7) + ((lane>>4)&1)*8,
    // col = ((lane>>3)&1)*4 -> r0,r1 = tile 2j {b0,b1}; r2,r3 = tile 2j+1.
    const int bRow = (lane & 7) + ((lane >> 4) & 1) * 8;
    const int bCol = ((lane >> 3) & 1) * 4;
    uint32_t bAddr[2];
    #pragma unroll
    for (int j = 0; j < 2; j++)
        bAddr[j] = smem_u32(Ws + (nBase + j * 16 + bRow) * LDSTR + bCol);

    float acc[4][4][4];
    #pragma unroll
    for (int mt = 0; mt < 4; mt++)
        #pragma unroll
        for (int nt = 0; nt < 4; nt++)
            #pragma unroll
            for (int r = 0; r < 4; r++) acc[mt][nt][r] = 0.0f;

    #pragma unroll
    for (int ks = 0; ks < 16; ks++) {
        const uint32_t koff = ks * 32;   // 8 floats = 32 bytes
        uint32_t a[4][4];
        #pragma unroll
        for (int mt = 0; mt < 4; mt++)
            ldsm_x4(a[mt][0], a[mt][1], a[mt][2], a[mt][3], aAddr[mt] + koff);
        uint32_t b[4][2];
        #pragma unroll
        for (int j = 0; j < 2; j++)
            ldsm_x4(b[2*j][0], b[2*j][1], b[2*j+1][0], b[2*j+1][1], bAddr[j] + koff);
        #pragma unroll
        for (int mt = 0; mt < 4; mt++)
            #pragma unroll
            for (int nt = 0; nt < 4; nt++)
                mma_tf32(acc[mt][nt], a[mt], b[nt]);
    }

    // Write: c0/c1 -> (row g, cols 2*tig,2*tig+1); c2/c3 -> row g+8.
    #pragma unroll
    for (int mt = 0; mt < 4; mt++) {
        int r0 = rowBase + mt * 16 + g;
        int r1 = r0 + 8;
        #pragma unroll
        for (int nt = 0; nt < 4; nt++) {
            int c = nBase + nt * 8 + tig * 2;
            if (r0 < M)
                *reinterpret_cast<float2*>(O + (size_t)r0 * OUT_F + c) =
                    make_float2(acc[mt][nt][0], acc[mt][nt][1]);
            if (r1 < M)
                *reinterpret_cast<float2*>(O + (size_t)r1 * OUT_F + c) =
                    make_float2(acc[mt][nt][2], acc[mt][nt][3]);
        }
    }
}

// ---- K2: gather h from O, compute attn, stage contribution -----------------
__global__ __launch_bounds__(128) void gat_edge_gather(
    const float* __restrict__ O,
    const int* __restrict__ EI,        // [2,E]: row0 src, row1 dst
    const float* __restrict__ A,       // [HEADS, 2*HDIM]
    int E)
{
    const int e = blockIdx.x;
    const int tid = threadIdx.x;
    const int src = EI[e];
    const int dst = EI[E + e];

    float hs = O[(size_t)src * OUT_F + tid];
    float hd = O[(size_t)dst * OUT_F + tid];

    const int h = tid >> 5;
    const int d = tid & 31;
    float ev = hs * A[h * (2 * HDIM) + d] + hd * A[h * (2 * HDIM) + HDIM + d];
    #pragma unroll
    for (int off = 16; off > 0; off >>= 1)
        ev += __shfl_xor_sync(0xffffffffu, ev, off);
    float attn = ev > 0.0f ? ev : 0.2f * ev;

    g_contrib[e * OUT_F + tid] = 0.1f * attn * hs;
}

// ---- K3: scatter staged contributions --------------------------------------
__global__ __launch_bounds__(128) void gat_edge_scatter(
    float* __restrict__ O,
    const int* __restrict__ EI,
    int E)
{
    const int e = blockIdx.x;
    const int tid = threadIdx.x;
    const int dst = EI[E + e];
    atomicAdd(&O[(size_t)dst * OUT_F + tid], g_contrib[e * OUT_F + tid]);
}

extern "C" void kernel_launch(void* const* d_in, const int* in_sizes, int n_in,
                              void* d_out, int out_size)
{
    const float* x  = (const float*)d_in[0];
    const int*   ei = (const int*)d_in[1];
    const float* W  = (const float*)d_in[2];
    const float* a  = (const float*)d_in[3];
    float* out = (float*)d_out;

    const int M = in_sizes[0] / IN_F;   // 200000
    int E = in_sizes[1] / 2;            // 500
    if (E > MAX_E) E = MAX_E;

    const int smemBytes = (BM + IN_F) * LDSTR * sizeof(uint32_t);  // ~99KB
    cudaFuncSetAttribute(gat_gemm_tf32,
                         cudaFuncAttributeMaxDynamicSharedMemorySize, smemBytes);

    const int grid = (M + BM - 1) / BM;
    gat_gemm_tf32<<<grid, 128, smemBytes>>>(x, W, out, M);
    gat_edge_gather<<<E, 128>>>(out, ei, a, E);
    gat_edge_scatter<<<E, 128>>>(out, ei, E);
}

// round 8
// speedup vs baseline: 4.9037x; 1.2688x over previous
#include <cuda_runtime.h>
#include <cuda_bf16.h>
#include <cstdint>

// ---------------------------------------------------------------------------
// GAT layer, tf32 tensor cores, persistent CTAs + cp.async double buffering.
//   K1: h = x @ W.T. 148 persistent CTAs (1/SM), 256 thr, BM=128 tiles.
//       W staged+tf32-converted once per CTA; A tiles prefetched with
//       cp.async (raw fp32), fragments converted to tf32 in registers.
//   K2: per edge, read h[src],h[dst] from d_out (pre-scatter), attention,
//       stage 0.1*attn*h_src into scratch.
//   K3: atomicAdd staged contributions into d_out[dst].
// edge_index is int32 (jax x64 disabled).
// ---------------------------------------------------------------------------

#define IN_F  128
#define OUT_F 128
#define HEADS 4
#define HDIM  32

#define BM    128
#define LDSTR 132     // row stride (floats) = 528B; LDSM rows -> distinct 16B banks
#define NCTA  148

#define MAX_E 2048
__device__ float g_contrib[MAX_E * OUT_F];

__device__ __forceinline__ uint32_t f2tf32(float f) {
    uint32_t u;
    asm("cvt.rna.tf32.f32 %0, %1;" : "=r"(u) : "f"(f));
    return u;
}

__device__ __forceinline__ uint32_t smem_u32(const void* p) {
    uint32_t a;
    asm("{ .reg .u64 t; cvta.to.shared.u64 t, %1; cvt.u32.u64 %0, t; }"
        : "=r"(a) : "l"(p));
    return a;
}

__device__ __forceinline__ void ldsm_x4(uint32_t& r0, uint32_t& r1,
                                        uint32_t& r2, uint32_t& r3,
                                        uint32_t addr) {
    asm volatile("ldmatrix.sync.aligned.m8n8.x4.shared.b16 {%0,%1,%2,%3}, [%4];"
                 : "=r"(r0), "=r"(r1), "=r"(r2), "=r"(r3) : "r"(addr));
}

__device__ __forceinline__ void mma_tf32(float* c, const uint32_t* a, const uint32_t* b) {
    asm volatile(
        "mma.sync.aligned.m16n8k8.row.col.f32.tf32.tf32.f32 "
        "{%0,%1,%2,%3}, {%4,%5,%6,%7}, {%8,%9}, {%0,%1,%2,%3};"
        : "+f"(c[0]), "+f"(c[1]), "+f"(c[2]), "+f"(c[3])
        : "r"(a[0]), "r"(a[1]), "r"(a[2]), "r"(a[3]), "r"(b[0]), "r"(b[1]));
}

__device__ __forceinline__ void cpasync16(uint32_t dst, const void* src) {
    asm volatile("cp.async.cg.shared.global [%0], [%1], 16;" :: "r"(dst), "l"(src));
}

// Prefetch one 128x128 fp32 A tile (raw bits) into buf. 16 x 16B per thread.
__device__ __forceinline__ void prefetch_tile(
    const float* __restrict__ X, int rowBase, int M, uint32_t bufAddr, int tid)
{
    #pragma unroll
    for (int i = 0; i < 16; i++) {
        int fid = tid + i * 256;
        int row = fid >> 5, c4 = fid & 31;
        int gr = rowBase + row; if (gr >= M) gr = M - 1;
        cpasync16(bufAddr + (uint32_t)(row * LDSTR + c4 * 4) * 4,
                  X + (size_t)gr * IN_F + c4 * 4);
    }
}

// ---- K1: persistent tf32 GEMM ----------------------------------------------
__global__ __launch_bounds__(256, 1) void gat_gemm_tf32(
    const float* __restrict__ X,   // [M,128]
    const float* __restrict__ W,   // [128,128] row-major (out = X * W^T)
    float* __restrict__ O,         // [M,128]
    int M)
{
    extern __shared__ uint32_t smem[];
    uint32_t* A0 = smem;                         // [128][LDSTR] buffer 0
    uint32_t* A1 = smem + BM * LDSTR;            // buffer 1
    uint32_t* Ws = smem + 2 * BM * LDSTR;        // [128][LDSTR] tf32 W

    const int tid = threadIdx.x;
    const int nTiles = (M + BM - 1) / BM;
    const uint32_t aBuf[2] = { smem_u32(A0), smem_u32(A1) };

    // Prologue: prefetch first tile into buf0, then stage+convert W.
    int t0 = blockIdx.x;
    if (t0 < nTiles) {
        prefetch_tile(X, t0 * BM, M, aBuf[0], tid);
        asm volatile("cp.async.commit_group;" ::: "memory");
    }
    #pragma unroll
    for (int i = 0; i < 16; i++) {
        int fid = tid + i * 256;
        int n = fid >> 5, c4 = fid & 31;
        float4 v = *reinterpret_cast<const float4*>(W + (size_t)n * IN_F + c4 * 4);
        uint4 t = make_uint4(f2tf32(v.x), f2tf32(v.y), f2tf32(v.z), f2tf32(v.w));
        *reinterpret_cast<uint4*>(Ws + n * LDSTR + c4 * 4) = t;
    }

    const int warp = tid >> 5, lane = tid & 31;
    const int mw = warp >> 1, nw = warp & 1;     // 4 M-warps x 2 N-warps
    const int g = lane >> 2, tig = lane & 3;

    // LDSM lane addresses (A addr recomputed per buffer via offset).
    const int aRow = (lane & 7) + ((lane >> 3) & 1) * 8;
    const int aCol = ((lane >> 4) & 1) * 4;
    uint32_t aOff[2];   // byte offset within a buffer, per m-tile
    #pragma unroll
    for (int mt = 0; mt < 2; mt++)
        aOff[mt] = (uint32_t)((mw * 32 + mt * 16 + aRow) * LDSTR + aCol) * 4;

    const int bRow = (lane & 7) + ((lane >> 4) & 1) * 8;
    const int bCol = ((lane >> 3) & 1) * 4;
    uint32_t bAddr[4];
    #pragma unroll
    for (int j = 0; j < 4; j++)
        bAddr[j] = smem_u32(Ws + (nw * 64 + j * 16 + bRow) * LDSTR + bCol);

    int it = 0;
    for (int t = t0; t < nTiles; t += NCTA, it++) {
        const uint32_t cur = aBuf[it & 1];
        const uint32_t nxt = aBuf[(it + 1) & 1];

        asm volatile("cp.async.wait_group 0;" ::: "memory");
        __syncthreads();                       // tile data + W visible; prev
                                               // compute on 'nxt' buffer done
        int tn = t + NCTA;
        if (tn < nTiles) {
            prefetch_tile(X, tn * BM, M, nxt, tid);
            asm volatile("cp.async.commit_group;" ::: "memory");
        }

        float acc[2][8][4];
        #pragma unroll
        for (int mt = 0; mt < 2; mt++)
            #pragma unroll
            for (int nt = 0; nt < 8; nt++)
                #pragma unroll
                for (int r = 0; r < 4; r++) acc[mt][nt][r] = 0.0f;

        #pragma unroll
        for (int ks = 0; ks < 16; ks++) {
            const uint32_t koff = ks * 32;
            uint32_t a[2][4];
            #pragma unroll
            for (int mt = 0; mt < 2; mt++)
                ldsm_x4(a[mt][0], a[mt][1], a[mt][2], a[mt][3],
                        cur + aOff[mt] + koff);
            uint32_t b[8][2];
            #pragma unroll
            for (int j = 0; j < 4; j++)
                ldsm_x4(b[2*j][0], b[2*j][1], b[2*j+1][0], b[2*j+1][1],
                        bAddr[j] + koff);
            // A arrived as raw fp32: convert fragments to tf32 (rna).
            #pragma unroll
            for (int mt = 0; mt < 2; mt++)
                #pragma unroll
                for (int r = 0; r < 4; r++)
                    a[mt][r] = f2tf32(__uint_as_float(a[mt][r]));
            #pragma unroll
            for (int mt = 0; mt < 2; mt++)
                #pragma unroll
                for (int nt = 0; nt < 8; nt++)
                    mma_tf32(acc[mt][nt], a[mt], b[nt]);
        }

        // Epilogue: c0/c1 -> (row g, cols 2tig,2tig+1); c2/c3 -> row g+8.
        const int rowBase = t * BM + mw * 32;
        #pragma unroll
        for (int mt = 0; mt < 2; mt++) {
            int r0 = rowBase + mt * 16 + g;
            int r1 = r0 + 8;
            #pragma unroll
            for (int nt = 0; nt < 8; nt++) {
                int c = nw * 64 + nt * 8 + tig * 2;
                if (r0 < M)
                    *reinterpret_cast<float2*>(O + (size_t)r0 * OUT_F + c) =
                        make_float2(acc[mt][nt][0], acc[mt][nt][1]);
                if (r1 < M)
                    *reinterpret_cast<float2*>(O + (size_t)r1 * OUT_F + c) =
                        make_float2(acc[mt][nt][2], acc[mt][nt][3]);
            }
        }
        __syncthreads();   // all LDSM on 'cur' done before it is refilled
    }
}

// ---- K2: gather h from O, compute attn, stage contribution -----------------
__global__ __launch_bounds__(128) void gat_edge_gather(
    const float* __restrict__ O,
    const int* __restrict__ EI,        // [2,E]: row0 src, row1 dst
    const float* __restrict__ A,       // [HEADS, 2*HDIM]
    int E)
{
    const int e = blockIdx.x;
    const int tid = threadIdx.x;
    const int src = EI[e];
    const int dst = EI[E + e];

    float hs = O[(size_t)src * OUT_F + tid];
    float hd = O[(size_t)dst * OUT_F + tid];

    const int h = tid >> 5;
    const int d = tid & 31;
    float ev = hs * A[h * (2 * HDIM) + d] + hd * A[h * (2 * HDIM) + HDIM + d];
    #pragma unroll
    for (int off = 16; off > 0; off >>= 1)
        ev += __shfl_xor_sync(0xffffffffu, ev, off);
    float attn = ev > 0.0f ? ev : 0.2f * ev;

    g_contrib[e * OUT_F + tid] = 0.1f * attn * hs;
}

// ---- K3: scatter staged contributions --------------------------------------
__global__ __launch_bounds__(128) void gat_edge_scatter(
    float* __restrict__ O,
    const int* __restrict__ EI,
    int E)
{
    const int e = blockIdx.x;
    const int tid = threadIdx.x;
    const int dst = EI[E + e];
    atomicAdd(&O[(size_t)dst * OUT_F + tid], g_contrib[e * OUT_F + tid]);
}

extern "C" void kernel_launch(void* const* d_in, const int* in_sizes, int n_in,
                              void* d_out, int out_size)
{
    const float* x  = (const float*)d_in[0];
    const int*   ei = (const int*)d_in[1];
    const float* W  = (const float*)d_in[2];
    const float* a  = (const float*)d_in[3];
    float* out = (float*)d_out;

    const int M = in_sizes[0] / IN_F;   // 200000
    int E = in_sizes[1] / 2;            // 500
    if (E > MAX_E) E = MAX_E;

    const int smemBytes = 3 * BM * LDSTR * sizeof(uint32_t);  // ~198KB
    cudaFuncSetAttribute(gat_gemm_tf32,
                         cudaFuncAttributeMaxDynamicSharedMemorySize, smemBytes);

    gat_gemm_tf32<<<NCTA, 256, smemBytes>>>(x, W, out, M);
    gat_edge_gather<<<E, 128>>>(out, ei, a, E);
    gat_edge_scatter<<<E, 128>>>(out, ei, E);
}